// round 2
// baseline (speedup 1.0000x reference)
#include <cuda_runtime.h>

// Problem constants (fixed by the dataset)
#define Nn 10000
#define Tt 6
#define Ff 64
#define Ee 160000
#define EP 170000   // Ee + Nn self loops

// ---------------- scratch (device globals; no allocations allowed) -------------
__device__ __align__(16) float g_xw0[Nn * 64];
__device__ __align__(16) float g_h0[Nn * 64];
__device__ __align__(16) float g_xw1[Nn * 256];
__device__ __align__(16) float g_ssrc[Nn * 4];
__device__ __align__(16) float g_sdst[Nn * 4];
__device__ __align__(16) float g_lg[EP * 4];
__device__ __align__(16) float g_alpha[EP * 4];
__device__ __align__(16) float g_ht[Nn * 64];
__device__ __align__(16) float g_hgru[Nn * 64];
__device__ __align__(16) float g_Wt_ih[192 * 64];
__device__ __align__(16) float g_Wt_hh[192 * 64];
__device__ int g_deg[Nn];
__device__ int g_rowptr[Nn + 1];
__device__ int g_cursor[Nn];
__device__ int g_csr_src[EP];
__device__ int g_csr_dst[EP];
__device__ int g_csr_eid[EP];
__device__ int g_is64;

// ---------------- edge-index dtype detection ------------------------------------
// If the buffer is little-endian int64, every odd 32-bit word is a high word == 0
// (values < 10000). If it is int32, odd words are random node ids (~never 0).
__global__ void k_detect(const int* __restrict__ ei32) {
    if (threadIdx.x == 0 && blockIdx.x == 0) {
        int zeros = 0;
        for (int i = 0; i < 64; i++)
            if (ei32[2 * i + 1] == 0) zeros++;
        g_is64 = (zeros > 32) ? 1 : 0;
    }
}

__device__ __forceinline__ int edge_val(const void* ei, int idx) {
    if (g_is64) return (int)((const long long*)ei)[idx];
    return ((const int*)ei)[idx];
}

// ---------------- init ----------------------------------------------------------
__global__ void k_init() {
    int i = blockIdx.x * 256 + threadIdx.x;
    if (i < Nn * 64) g_hgru[i] = 0.0f;
    if (i < Nn) g_deg[i] = 0;
}

// Transpose GRU weights: Wt[j][gate*64+k] = W[(gate*64+k)*64 + j]
__global__ void k_transpose(const float* __restrict__ W_ih, const float* __restrict__ W_hh) {
    int i = blockIdx.x * 256 + threadIdx.x;
    if (i >= 192 * 64) return;
    int kk = i / 64, j = i % 64;
    g_Wt_ih[j * 192 + kk] = W_ih[i];
    g_Wt_hh[j * 192 + kk] = W_hh[i];
}

// ---------------- CSR build (dst-major) -----------------------------------------
__global__ void k_count(const void* __restrict__ ei) {
    int e = blockIdx.x * 256 + threadIdx.x;
    if (e >= EP) return;
    int d = (e < Ee) ? edge_val(ei, Ee + e) : (e - Ee);
    atomicAdd(&g_deg[d], 1);
}

__global__ void k_scan() {
    __shared__ int wsum[32];
    int tid = threadIdx.x;
    const int IT = 10;  // 1024*10 >= 10000
    int base = tid * IT;
    int vals[IT];
    int s = 0;
#pragma unroll
    for (int i = 0; i < IT; i++) {
        int idx = base + i;
        int v = (idx < Nn) ? g_deg[idx] : 0;
        vals[i] = s;
        s += v;
    }
    int lane = tid & 31, w = tid >> 5;
    int inc = s;
    for (int o = 1; o < 32; o <<= 1) {
        int y = __shfl_up_sync(0xffffffffu, inc, o);
        if (lane >= o) inc += y;
    }
    if (lane == 31) wsum[w] = inc;
    __syncthreads();
    if (w == 0) {
        int v = wsum[lane];
        for (int o = 1; o < 32; o <<= 1) {
            int y = __shfl_up_sync(0xffffffffu, v, o);
            if (lane >= o) v += y;
        }
        wsum[lane] = v;
    }
    __syncthreads();
    int excl = inc - s + ((w > 0) ? wsum[w - 1] : 0);
#pragma unroll
    for (int i = 0; i < IT; i++) {
        int idx = base + i;
        if (idx < Nn) {
            g_rowptr[idx] = excl + vals[i];
            g_cursor[idx] = excl + vals[i];
        }
    }
    if (tid == 1023) g_rowptr[Nn] = wsum[31];
}

__global__ void k_scatter(const void* __restrict__ ei) {
    int e = blockIdx.x * 256 + threadIdx.x;
    if (e >= EP) return;
    int s = (e < Ee) ? edge_val(ei, e) : (e - Ee);
    int d = (e < Ee) ? edge_val(ei, Ee + e) : (e - Ee);
    int p = atomicAdd(&g_cursor[d], 1);
    g_csr_src[p] = s;
    g_csr_dst[p] = d;
    g_csr_eid[p] = e;
}

// ---------------- GAT layer 0 GEMM + head sums ----------------------------------
// xw0 = x_t @ W0 ([N,64]x[64,64]); ssrc[n,h]=sum_c xw0[n,h*16+c]*a_src0[h*16+c]
__global__ void k_l0_gemm(const float* __restrict__ x, const float* __restrict__ W0,
                          const float* __restrict__ a_src, const float* __restrict__ a_dst,
                          int t) {
    __shared__ float sW[64 * 64];
    __shared__ float sx[4][64];
    int tid = threadIdx.x;
    int n0 = blockIdx.x * 4;
    for (int i = tid; i < 64 * 64; i += 256) sW[i] = W0[i];
    int r = tid >> 6, c = tid & 63;
    int n = n0 + r;
    sx[r][c] = x[(size_t)n * (Tt * Ff) + t * Ff + c];
    __syncthreads();
    float acc = 0.f;
#pragma unroll 16
    for (int j = 0; j < 64; j++) acc += sx[r][j] * sW[j * 64 + c];
    g_xw0[n * 64 + c] = acc;
    float pr = acc * a_src[c];
    float pd = acc * a_dst[c];
#pragma unroll
    for (int o = 8; o > 0; o >>= 1) {
        pr += __shfl_down_sync(0xffffffffu, pr, o);
        pd += __shfl_down_sync(0xffffffffu, pd, o);
    }
    if ((c & 15) == 0) {
        g_ssrc[n * 4 + (c >> 4)] = pr;
        g_sdst[n * 4 + (c >> 4)] = pd;
    }
}

// ---------------- GAT layer 1 GEMM + head sums ----------------------------------
// xw1 = h0 @ W1 ([N,64]x[64,256]); ssrc[n,h]=sum_c xw1[n,h*64+c]*a_src1[h*64+c]
__global__ void k_l1_gemm(const float* __restrict__ W1, const float* __restrict__ a_src,
                          const float* __restrict__ a_dst) {
    int tid = threadIdx.x;
    int n0 = blockIdx.x * 4;
    __shared__ float sx[4][64];
    int r = tid >> 6, c = tid & 63;
    sx[r][c] = g_h0[(n0 + r) * 64 + c];
    __syncthreads();
    float acc[4] = {0.f, 0.f, 0.f, 0.f};
    for (int j = 0; j < 64; j++) {
        float w = W1[j * 256 + tid];
#pragma unroll
        for (int r2 = 0; r2 < 4; r2++) acc[r2] += sx[r2][j] * w;
    }
    float as = a_src[tid], ad = a_dst[tid];
    int lane = tid & 31, w8 = tid >> 5;
    __shared__ float rs[4][8], rd[4][8];
#pragma unroll
    for (int r2 = 0; r2 < 4; r2++) {
        g_xw1[(size_t)(n0 + r2) * 256 + tid] = acc[r2];
        float pr = acc[r2] * as, pd = acc[r2] * ad;
#pragma unroll
        for (int o = 16; o > 0; o >>= 1) {
            pr += __shfl_down_sync(0xffffffffu, pr, o);
            pd += __shfl_down_sync(0xffffffffu, pd, o);
        }
        if (lane == 0) { rs[r2][w8] = pr; rd[r2][w8] = pd; }
    }
    __syncthreads();
    if (tid < 16) {
        int r2 = tid >> 2, h = tid & 3;
        g_ssrc[(n0 + r2) * 4 + h] = rs[r2][2 * h] + rs[r2][2 * h + 1];
        g_sdst[(n0 + r2) * 4 + h] = rd[r2][2 * h] + rd[r2][2 * h + 1];
    }
}

// ---------------- edge logits (both layers share buffers) -----------------------
__global__ void k_edge_logit() {
    int p = blockIdx.x * 256 + threadIdx.x;
    if (p >= EP) return;
    int s = g_csr_src[p], d = g_csr_dst[p];
    float4 a = ((const float4*)g_ssrc)[s];
    float4 b = ((const float4*)g_sdst)[d];
    float4 l;
    l.x = a.x + b.x; l.x = l.x > 0.f ? l.x : 0.2f * l.x;
    l.y = a.y + b.y; l.y = l.y > 0.f ? l.y : 0.2f * l.y;
    l.z = a.z + b.z; l.z = l.z > 0.f ? l.z : 0.2f * l.z;
    l.w = a.w + b.w; l.w = l.w > 0.f ? l.w : 0.2f * l.w;
    ((float4*)g_lg)[p] = l;
}

// ---------------- segment softmax per (dst node, head) --------------------------
__global__ void k_softmax() {
    int i = blockIdx.x * 256 + threadIdx.x;
    if (i >= Nn * 4) return;
    int d = i >> 2, h = i & 3;
    int p0 = g_rowptr[d], p1 = g_rowptr[d + 1];
    float m = -1e30f;
    for (int p = p0; p < p1; p++) m = fmaxf(m, g_lg[p * 4 + h]);
    float ssum = 0.f;
    for (int p = p0; p < p1; p++) ssum += expf(g_lg[p * 4 + h] - m);
    float inv = 1.f / (ssum + 1e-16f);
    for (int p = p0; p < p1; p++) g_alpha[p * 4 + h] = expf(g_lg[p * 4 + h] - m) * inv;
}

// ---------------- layer-0 aggregation + bias + elu -> h0 ------------------------
__global__ void k_aggr0(const float* __restrict__ b0) {
    int d = blockIdx.x;
    int c = threadIdx.x;  // 64
    int h = c >> 4;
    int p0 = g_rowptr[d], p1 = g_rowptr[d + 1];
    float acc = 0.f;
    for (int p = p0; p < p1; p++) {
        float4 al = ((const float4*)g_alpha)[p];
        float a = (h == 0) ? al.x : (h == 1) ? al.y : (h == 2) ? al.z : al.w;
        acc += a * g_xw0[g_csr_src[p] * 64 + c];
    }
    float v = acc + b0[c];
    v = (v > 0.f) ? v : expm1f(v);
    g_h0[d * 64 + c] = v;
}

// ---------------- layer-1 aggregation + head-mean + bias + elu + LN -> ht -------
__global__ void k_aggr1(const float* __restrict__ b1, const float* __restrict__ ln_g,
                        const float* __restrict__ ln_b) {
    int d = blockIdx.x;
    int tid = threadIdx.x;  // 256
    int h = tid >> 6;
    int p0 = g_rowptr[d], p1 = g_rowptr[d + 1];
    float acc = 0.f;
    for (int p = p0; p < p1; p++) {
        float4 al = ((const float4*)g_alpha)[p];
        float a = (h == 0) ? al.x : (h == 1) ? al.y : (h == 2) ? al.z : al.w;
        acc += a * g_xw1[(size_t)g_csr_src[p] * 256 + tid];
    }
    __shared__ float sh[256];
    __shared__ float row[64];
    __shared__ float ps[2], ps2[2];
    sh[tid] = acc;
    __syncthreads();
    if (tid < 64) {
        float v = (sh[tid] + sh[tid + 64] + sh[tid + 128] + sh[tid + 192]) * 0.25f + b1[tid];
        v = (v > 0.f) ? v : expm1f(v);
        row[tid] = v;
        float s = v, q = v * v;
#pragma unroll
        for (int o = 16; o > 0; o >>= 1) {
            s += __shfl_down_sync(0xffffffffu, s, o);
            q += __shfl_down_sync(0xffffffffu, q, o);
        }
        if ((tid & 31) == 0) { ps[tid >> 5] = s; ps2[tid >> 5] = q; }
    }
    __syncthreads();
    if (tid < 64) {
        float mean = (ps[0] + ps[1]) * (1.f / 64.f);
        float var = (ps2[0] + ps2[1]) * (1.f / 64.f) - mean * mean;
        float v = (row[tid] - mean) * rsqrtf(var + 1e-5f);
        g_ht[d * 64 + tid] = v * ln_g[tid] + ln_b[tid];
    }
}

// ---------------- GRU step ------------------------------------------------------
__global__ void k_gru(const float* __restrict__ b_ih, const float* __restrict__ b_hh,
                      float* __restrict__ outp) {
    int tid = threadIdx.x;  // 256 = 4 rows x 64
    int r = tid >> 6, k = tid & 63;
    int n = blockIdx.x * 4 + r;
    __shared__ float sx[4][64], shh[4][64];
    sx[r][k] = g_ht[n * 64 + k];
    shh[r][k] = g_hgru[n * 64 + k];
    __syncthreads();
    float ai0 = 0.f, ai1 = 0.f, ai2 = 0.f;
    float ah0 = 0.f, ah1 = 0.f, ah2 = 0.f;
    for (int j = 0; j < 64; j++) {
        float xv = sx[r][j], hv = shh[r][j];
        const float* wi = &g_Wt_ih[j * 192];
        const float* wh = &g_Wt_hh[j * 192];
        ai0 += xv * wi[k];        ah0 += hv * wh[k];
        ai1 += xv * wi[64 + k];   ah1 += hv * wh[64 + k];
        ai2 += xv * wi[128 + k];  ah2 += hv * wh[128 + k];
    }
    float ir = ai0 + b_ih[k],       hr = ah0 + b_hh[k];
    float iz = ai1 + b_ih[64 + k],  hz = ah1 + b_hh[64 + k];
    float ig = ai2 + b_ih[128 + k], hg = ah2 + b_hh[128 + k];
    float rr = 1.f / (1.f + expf(-(ir + hr)));
    float zz = 1.f / (1.f + expf(-(iz + hz)));
    float gg = tanhf(ig + rr * hg);
    float hn = (1.f - zz) * gg + zz * shh[r][k];
    g_hgru[n * 64 + k] = hn;
    if (outp) outp[n * 64 + k] = hn;
}

// ---------------- output writers ------------------------------------------------
__global__ void k_write_alpha(float* __restrict__ out) {
    int p = blockIdx.x * 256 + threadIdx.x;
    if (p >= EP) return;
    float4 a = ((const float4*)g_alpha)[p];
    int e = g_csr_eid[p];
    ((float4*)(out + (size_t)Nn * 64))[e] = a;
}

// mode 0: write indices as float32 (2*EP elements)
// mode 1: write indices as raw int64 (occupies 4*EP float slots)
__global__ void k_write_edges(const void* __restrict__ ei, float* __restrict__ out,
                              int mode) {
    int e = blockIdx.x * 256 + threadIdx.x;
    if (e >= EP) return;
    int s = (e < Ee) ? edge_val(ei, e) : (e - Ee);
    int d = (e < Ee) ? edge_val(ei, Ee + e) : (e - Ee);
    size_t base = (size_t)Nn * 64 + (size_t)EP * 4;
    if (mode == 1) {
        long long* p = (long long*)(out + base);
        p[e] = (long long)s;
        p[EP + e] = (long long)d;
    } else {
        out[base + e] = (float)s;
        out[base + EP + e] = (float)d;
    }
}

// ---------------- host launch ---------------------------------------------------
extern "C" void kernel_launch(void* const* d_in, const int* in_sizes, int n_in,
                              void* d_out, int out_size) {
    const float* x        = (const float*)d_in[0];
    const void*  ei       = (const void*)d_in[1];
    const float* W0       = (const float*)d_in[2];
    const float* a_src0   = (const float*)d_in[3];
    const float* a_dst0   = (const float*)d_in[4];
    const float* b0       = (const float*)d_in[5];
    const float* W1       = (const float*)d_in[6];
    const float* a_src1   = (const float*)d_in[7];
    const float* a_dst1   = (const float*)d_in[8];
    const float* b1       = (const float*)d_in[9];
    const float* ln_g     = (const float*)d_in[10];
    const float* ln_b     = (const float*)d_in[11];
    const float* W_ih     = (const float*)d_in[12];
    const float* W_hh     = (const float*)d_in[13];
    const float* b_ih     = (const float*)d_in[14];
    const float* b_hh     = (const float*)d_in[15];

    float* out = (float*)d_out;

    const int EB = (EP + 255) / 256;      // edge-grid
    const int NB4 = Nn / 4;               // 4-row blocks

    k_detect<<<1, 32>>>((const int*)ei);
    k_init<<<(Nn * 64 + 255) / 256, 256>>>();
    k_transpose<<<(192 * 64 + 255) / 256, 256>>>(W_ih, W_hh);
    k_count<<<EB, 256>>>(ei);
    k_scan<<<1, 1024>>>();
    k_scatter<<<EB, 256>>>(ei);

    for (int t = 0; t < Tt; t++) {
        // layer 0
        k_l0_gemm<<<NB4, 256>>>(x, W0, a_src0, a_dst0, t);
        k_edge_logit<<<EB, 256>>>();
        k_softmax<<<(Nn * 4 + 255) / 256, 256>>>();
        k_aggr0<<<Nn, 64>>>(b0);
        // layer 1
        k_l1_gemm<<<NB4, 256>>>(W1, a_src1, a_dst1);
        k_edge_logit<<<EB, 256>>>();
        k_softmax<<<(Nn * 4 + 255) / 256, 256>>>();
        if (t == Tt - 1 && (long long)out_size >= (long long)Nn * 64 + (long long)EP * 4) {
            k_write_alpha<<<EB, 256>>>(out);
        }
        k_aggr1<<<Nn, 256>>>(b1, ln_g, ln_b);
        // GRU step
        float* outp = (t == Tt - 1) ? out : nullptr;
        k_gru<<<NB4, 256>>>(b_ih, b_hh, outp);
    }

    long long tail = (long long)out_size - ((long long)Nn * 64 + (long long)EP * 4);
    if (tail >= 4LL * EP) {
        k_write_edges<<<EB, 256>>>(ei, out, 1);
    } else if (tail >= 2LL * EP) {
        k_write_edges<<<EB, 256>>>(ei, out, 0);
    }
}

// round 3
// speedup vs baseline: 1.3982x; 1.3982x over previous
#include <cuda_runtime.h>

// Problem constants (fixed by the dataset)
#define Nn 10000
#define Tt 6
#define Ff 64
#define Ee 160000
#define EP 170000   // Ee + Nn self loops

// ---------------- scratch (device globals; no allocations allowed) -------------
__device__ __align__(16) float g_xw0[Nn * 64];
__device__ __align__(16) float g_h0[Nn * 64];
__device__ __align__(16) float g_xw1[Nn * 256];
__device__ __align__(16) float g_ssrc[Nn * 4];
__device__ __align__(16) float g_sdst[Nn * 4];
__device__ __align__(16) float g_lg[EP * 4];
__device__ __align__(16) float g_alpha[EP * 4];
__device__ __align__(16) float g_ht[Nn * 64];
__device__ __align__(16) float g_hgru[Nn * 64];
__device__ __align__(16) float g_Wt_ih[192 * 64];
__device__ __align__(16) float g_Wt_hh[192 * 64];
__device__ int g_deg[Nn];
__device__ int g_rowptr[Nn + 1];
__device__ int g_cursor[Nn];
__device__ int g_csr_src[EP];
__device__ int g_csr_dst[EP];
__device__ int g_csr_eid[EP];
__device__ int g_is64;

// ---------------- edge-index dtype detection ------------------------------------
__global__ void k_detect(const int* __restrict__ ei32) {
    if (threadIdx.x == 0 && blockIdx.x == 0) {
        int zeros = 0;
        for (int i = 0; i < 64; i++)
            if (ei32[2 * i + 1] == 0) zeros++;
        g_is64 = (zeros > 32) ? 1 : 0;
    }
}

__device__ __forceinline__ int edge_val(const void* ei, int idx) {
    if (g_is64) return (int)((const long long*)ei)[idx];
    return ((const int*)ei)[idx];
}

// ---------------- init + GRU weight transpose -----------------------------------
__global__ void k_init(const float* __restrict__ W_ih, const float* __restrict__ W_hh) {
    int i = blockIdx.x * 256 + threadIdx.x;
    if (i < Nn * 64) g_hgru[i] = 0.0f;
    if (i < Nn) g_deg[i] = 0;
    if (i < 192 * 64) {
        int kk = i / 64, j = i % 64;
        g_Wt_ih[j * 192 + kk] = W_ih[i];
        g_Wt_hh[j * 192 + kk] = W_hh[i];
    }
}

// ---------------- CSR build (dst-major) -----------------------------------------
__global__ void k_count(const void* __restrict__ ei) {
    int e = blockIdx.x * 256 + threadIdx.x;
    if (e >= EP) return;
    int d = (e < Ee) ? edge_val(ei, Ee + e) : (e - Ee);
    atomicAdd(&g_deg[d], 1);
}

__global__ void k_scan() {
    __shared__ int wsum[32];
    int tid = threadIdx.x;
    const int IT = 10;
    int base = tid * IT;
    int vals[IT];
    int s = 0;
#pragma unroll
    for (int i = 0; i < IT; i++) {
        int idx = base + i;
        int v = (idx < Nn) ? g_deg[idx] : 0;
        vals[i] = s;
        s += v;
    }
    int lane = tid & 31, w = tid >> 5;
    int inc = s;
    for (int o = 1; o < 32; o <<= 1) {
        int y = __shfl_up_sync(0xffffffffu, inc, o);
        if (lane >= o) inc += y;
    }
    if (lane == 31) wsum[w] = inc;
    __syncthreads();
    if (w == 0) {
        int v = wsum[lane];
        for (int o = 1; o < 32; o <<= 1) {
            int y = __shfl_up_sync(0xffffffffu, v, o);
            if (lane >= o) v += y;
        }
        wsum[lane] = v;
    }
    __syncthreads();
    int excl = inc - s + ((w > 0) ? wsum[w - 1] : 0);
#pragma unroll
    for (int i = 0; i < IT; i++) {
        int idx = base + i;
        if (idx < Nn) {
            g_rowptr[idx] = excl + vals[i];
            g_cursor[idx] = excl + vals[i];
        }
    }
    if (tid == 1023) g_rowptr[Nn] = wsum[31];
}

__global__ void k_scatter(const void* __restrict__ ei) {
    int e = blockIdx.x * 256 + threadIdx.x;
    if (e >= EP) return;
    int s = (e < Ee) ? edge_val(ei, e) : (e - Ee);
    int d = (e < Ee) ? edge_val(ei, Ee + e) : (e - Ee);
    int p = atomicAdd(&g_cursor[d], 1);
    g_csr_src[p] = s;
    g_csr_dst[p] = d;
    g_csr_eid[p] = e;
}

// ---------------- GAT layer 0 GEMM + head sums (16 rows/block) ------------------
__global__ void k_l0_gemm(const float* __restrict__ x, const float* __restrict__ W0,
                          const float* __restrict__ a_src, const float* __restrict__ a_dst,
                          int t) {
    __shared__ float sW[64 * 64];
    __shared__ __align__(16) float sx[16][64];
    int tid = threadIdx.x;
    int n0 = blockIdx.x * 16;
    for (int i = tid; i < 64 * 64; i += 256) sW[i] = W0[i];
    for (int i = tid; i < 16 * 64; i += 256) {
        int r = i >> 6, c = i & 63;
        sx[r][c] = x[(size_t)(n0 + r) * (Tt * Ff) + t * Ff + c];
    }
    __syncthreads();
    int r4 = tid >> 6, c = tid & 63;
    float acc[4] = {0.f, 0.f, 0.f, 0.f};
#pragma unroll
    for (int j4 = 0; j4 < 16; j4++) {
        float w0 = sW[(4 * j4 + 0) * 64 + c];
        float w1 = sW[(4 * j4 + 1) * 64 + c];
        float w2 = sW[(4 * j4 + 2) * 64 + c];
        float w3 = sW[(4 * j4 + 3) * 64 + c];
#pragma unroll
        for (int q = 0; q < 4; q++) {
            float4 xv = *(const float4*)&sx[r4 + 4 * q][4 * j4];
            acc[q] += xv.x * w0 + xv.y * w1 + xv.z * w2 + xv.w * w3;
        }
    }
    float as = a_src[c], ad = a_dst[c];
#pragma unroll
    for (int q = 0; q < 4; q++) {
        int row = n0 + r4 + 4 * q;
        g_xw0[row * 64 + c] = acc[q];
        float pr = acc[q] * as, pd = acc[q] * ad;
#pragma unroll
        for (int o = 8; o > 0; o >>= 1) {
            pr += __shfl_down_sync(0xffffffffu, pr, o);
            pd += __shfl_down_sync(0xffffffffu, pd, o);
        }
        if ((c & 15) == 0) {
            g_ssrc[row * 4 + (c >> 4)] = pr;
            g_sdst[row * 4 + (c >> 4)] = pd;
        }
    }
}

// ---------------- GAT layer 1 GEMM + head sums (16 rows/block) ------------------
__global__ void k_l1_gemm(const float* __restrict__ W1, const float* __restrict__ a_src,
                          const float* __restrict__ a_dst) {
    __shared__ __align__(16) float sx[16][64];
    __shared__ float rs[16][8], rd[16][8];
    int tid = threadIdx.x;  // 256
    int n0 = blockIdx.x * 16;
    for (int i = tid; i < 16 * 64; i += 256) {
        int r = i >> 6, c = i & 63;
        sx[r][c] = g_h0[(n0 + r) * 64 + c];
    }
    __syncthreads();
    float acc[16];
#pragma unroll
    for (int r = 0; r < 16; r++) acc[r] = 0.f;
#pragma unroll 4
    for (int j4 = 0; j4 < 16; j4++) {
        float w0 = W1[(4 * j4 + 0) * 256 + tid];
        float w1 = W1[(4 * j4 + 1) * 256 + tid];
        float w2 = W1[(4 * j4 + 2) * 256 + tid];
        float w3 = W1[(4 * j4 + 3) * 256 + tid];
#pragma unroll
        for (int r = 0; r < 16; r++) {
            float4 xv = *(const float4*)&sx[r][4 * j4];
            acc[r] += xv.x * w0 + xv.y * w1 + xv.z * w2 + xv.w * w3;
        }
    }
    float as = a_src[tid], ad = a_dst[tid];
    int lane = tid & 31, w8 = tid >> 5;
#pragma unroll
    for (int r = 0; r < 16; r++) {
        g_xw1[(size_t)(n0 + r) * 256 + tid] = acc[r];
        float pr = acc[r] * as, pd = acc[r] * ad;
#pragma unroll
        for (int o = 16; o > 0; o >>= 1) {
            pr += __shfl_down_sync(0xffffffffu, pr, o);
            pd += __shfl_down_sync(0xffffffffu, pd, o);
        }
        if (lane == 0) { rs[r][w8] = pr; rd[r][w8] = pd; }
    }
    __syncthreads();
    if (tid < 64) {
        int r = tid >> 2, h = tid & 3;
        g_ssrc[(n0 + r) * 4 + h] = rs[r][2 * h] + rs[r][2 * h + 1];
        g_sdst[(n0 + r) * 4 + h] = rd[r][2 * h] + rd[r][2 * h + 1];
    }
}

// ---------------- fused edge-logit + segment softmax (warp per dst node) --------
// Phase 1: compute leaky-relu logits -> g_lg, track per-head max.
// Phase 2: exp(l - max) -> g_alpha (stash), accumulate sums.
// Phase 3: scale in place; optionally scatter to out (last timestep, layer 1).
__global__ void k_softmax_fused(float* __restrict__ outAlpha) {
    int gw = (blockIdx.x * 256 + threadIdx.x) >> 5;
    int lane = threadIdx.x & 31;
    if (gw >= Nn) return;
    int p0 = g_rowptr[gw], p1 = g_rowptr[gw + 1];
    float4 sd = ((const float4*)g_sdst)[gw];
    float m0 = -1e30f, m1 = -1e30f, m2 = -1e30f, m3 = -1e30f;
    for (int p = p0 + lane; p < p1; p += 32) {
        float4 a = ((const float4*)g_ssrc)[g_csr_src[p]];
        float l0 = a.x + sd.x; l0 = l0 > 0.f ? l0 : 0.2f * l0;
        float l1 = a.y + sd.y; l1 = l1 > 0.f ? l1 : 0.2f * l1;
        float l2 = a.z + sd.z; l2 = l2 > 0.f ? l2 : 0.2f * l2;
        float l3 = a.w + sd.w; l3 = l3 > 0.f ? l3 : 0.2f * l3;
        ((float4*)g_lg)[p] = make_float4(l0, l1, l2, l3);
        m0 = fmaxf(m0, l0); m1 = fmaxf(m1, l1);
        m2 = fmaxf(m2, l2); m3 = fmaxf(m3, l3);
    }
#pragma unroll
    for (int o = 16; o > 0; o >>= 1) {
        m0 = fmaxf(m0, __shfl_xor_sync(0xffffffffu, m0, o));
        m1 = fmaxf(m1, __shfl_xor_sync(0xffffffffu, m1, o));
        m2 = fmaxf(m2, __shfl_xor_sync(0xffffffffu, m2, o));
        m3 = fmaxf(m3, __shfl_xor_sync(0xffffffffu, m3, o));
    }
    float s0 = 0.f, s1 = 0.f, s2 = 0.f, s3 = 0.f;
    for (int p = p0 + lane; p < p1; p += 32) {
        float4 l = ((const float4*)g_lg)[p];
        float e0 = expf(l.x - m0), e1 = expf(l.y - m1);
        float e2 = expf(l.z - m2), e3 = expf(l.w - m3);
        ((float4*)g_alpha)[p] = make_float4(e0, e1, e2, e3);
        s0 += e0; s1 += e1; s2 += e2; s3 += e3;
    }
#pragma unroll
    for (int o = 16; o > 0; o >>= 1) {
        s0 += __shfl_xor_sync(0xffffffffu, s0, o);
        s1 += __shfl_xor_sync(0xffffffffu, s1, o);
        s2 += __shfl_xor_sync(0xffffffffu, s2, o);
        s3 += __shfl_xor_sync(0xffffffffu, s3, o);
    }
    float i0 = 1.f / (s0 + 1e-16f), i1 = 1.f / (s1 + 1e-16f);
    float i2 = 1.f / (s2 + 1e-16f), i3 = 1.f / (s3 + 1e-16f);
    for (int p = p0 + lane; p < p1; p += 32) {
        float4 e = ((const float4*)g_alpha)[p];
        e.x *= i0; e.y *= i1; e.z *= i2; e.w *= i3;
        ((float4*)g_alpha)[p] = e;
        if (outAlpha) ((float4*)outAlpha)[g_csr_eid[p]] = e;
    }
}

// ---------------- layer-0 aggregation + bias + elu -> h0 ------------------------
__global__ void k_aggr0(const float* __restrict__ b0) {
    int d = blockIdx.x;
    int c = threadIdx.x;  // 64
    int h = c >> 4;
    int p0 = g_rowptr[d], p1 = g_rowptr[d + 1];
    float acc = 0.f;
    int p = p0;
    for (; p + 4 <= p1; p += 4) {
        int s0 = g_csr_src[p], s1 = g_csr_src[p + 1];
        int s2 = g_csr_src[p + 2], s3 = g_csr_src[p + 3];
        float a0 = g_alpha[4 * p + h],       a1 = g_alpha[4 * (p + 1) + h];
        float a2 = g_alpha[4 * (p + 2) + h], a3 = g_alpha[4 * (p + 3) + h];
        float v0 = g_xw0[s0 * 64 + c], v1 = g_xw0[s1 * 64 + c];
        float v2 = g_xw0[s2 * 64 + c], v3 = g_xw0[s3 * 64 + c];
        acc += a0 * v0 + a1 * v1 + a2 * v2 + a3 * v3;
    }
    for (; p < p1; p++)
        acc += g_alpha[4 * p + h] * g_xw0[g_csr_src[p] * 64 + c];
    float v = acc + b0[c];
    v = (v > 0.f) ? v : expm1f(v);
    g_h0[d * 64 + c] = v;
}

// ---------------- layer-1 aggregation + head-mean + bias + elu + LN -> ht -------
__global__ void k_aggr1(const float* __restrict__ b1, const float* __restrict__ ln_g,
                        const float* __restrict__ ln_b) {
    int d = blockIdx.x;
    int tid = threadIdx.x;  // 256
    int h = tid >> 6;
    int p0 = g_rowptr[d], p1 = g_rowptr[d + 1];
    float acc = 0.f;
    int p = p0;
    for (; p + 4 <= p1; p += 4) {
        int s0 = g_csr_src[p], s1 = g_csr_src[p + 1];
        int s2 = g_csr_src[p + 2], s3 = g_csr_src[p + 3];
        float a0 = g_alpha[4 * p + h],       a1 = g_alpha[4 * (p + 1) + h];
        float a2 = g_alpha[4 * (p + 2) + h], a3 = g_alpha[4 * (p + 3) + h];
        float v0 = g_xw1[(size_t)s0 * 256 + tid], v1 = g_xw1[(size_t)s1 * 256 + tid];
        float v2 = g_xw1[(size_t)s2 * 256 + tid], v3 = g_xw1[(size_t)s3 * 256 + tid];
        acc += a0 * v0 + a1 * v1 + a2 * v2 + a3 * v3;
    }
    for (; p < p1; p++)
        acc += g_alpha[4 * p + h] * g_xw1[(size_t)g_csr_src[p] * 256 + tid];
    __shared__ float sh[256];
    __shared__ float row[64];
    __shared__ float ps[2], ps2[2];
    sh[tid] = acc;
    __syncthreads();
    if (tid < 64) {
        float v = (sh[tid] + sh[tid + 64] + sh[tid + 128] + sh[tid + 192]) * 0.25f + b1[tid];
        v = (v > 0.f) ? v : expm1f(v);
        row[tid] = v;
        float s = v, q = v * v;
#pragma unroll
        for (int o = 16; o > 0; o >>= 1) {
            s += __shfl_down_sync(0xffffffffu, s, o);
            q += __shfl_down_sync(0xffffffffu, q, o);
        }
        if ((tid & 31) == 0) { ps[tid >> 5] = s; ps2[tid >> 5] = q; }
    }
    __syncthreads();
    if (tid < 64) {
        float mean = (ps[0] + ps[1]) * (1.f / 64.f);
        float var = (ps2[0] + ps2[1]) * (1.f / 64.f) - mean * mean;
        float v = (row[tid] - mean) * rsqrtf(var + 1e-5f);
        g_ht[d * 64 + tid] = v * ln_g[tid] + ln_b[tid];
    }
}

// ---------------- GRU step: both GEMMs + gates in one kernel --------------------
// Block = 192 threads, 16 nodes. Thread k computes gate-column k (0..191).
__global__ void k_gru(const float* __restrict__ b_ih, const float* __restrict__ b_hh,
                      float* __restrict__ outp) {
    __shared__ __align__(16) float sx[16][64], sh[16][64];
    __shared__ float gi[16][192], gh[16][192];
    int tid = threadIdx.x;  // 192
    int n0 = blockIdx.x * 16;
    for (int i = tid; i < 16 * 64; i += 192) {
        int r = i >> 6, k = i & 63;
        sx[r][k] = g_ht[(n0 + r) * 64 + k];
        sh[r][k] = g_hgru[(n0 + r) * 64 + k];
    }
    __syncthreads();
    int k = tid;
    float ai[16], ah[16];
#pragma unroll
    for (int r = 0; r < 16; r++) { ai[r] = 0.f; ah[r] = 0.f; }
#pragma unroll 4
    for (int j4 = 0; j4 < 16; j4++) {
        float wi0 = g_Wt_ih[(4 * j4 + 0) * 192 + k];
        float wi1 = g_Wt_ih[(4 * j4 + 1) * 192 + k];
        float wi2 = g_Wt_ih[(4 * j4 + 2) * 192 + k];
        float wi3 = g_Wt_ih[(4 * j4 + 3) * 192 + k];
        float wh0 = g_Wt_hh[(4 * j4 + 0) * 192 + k];
        float wh1 = g_Wt_hh[(4 * j4 + 1) * 192 + k];
        float wh2 = g_Wt_hh[(4 * j4 + 2) * 192 + k];
        float wh3 = g_Wt_hh[(4 * j4 + 3) * 192 + k];
#pragma unroll
        for (int r = 0; r < 16; r++) {
            float4 xv = *(const float4*)&sx[r][4 * j4];
            float4 hv = *(const float4*)&sh[r][4 * j4];
            ai[r] += xv.x * wi0 + xv.y * wi1 + xv.z * wi2 + xv.w * wi3;
            ah[r] += hv.x * wh0 + hv.y * wh1 + hv.z * wh2 + hv.w * wh3;
        }
    }
    float bi = b_ih[k], bh = b_hh[k];
#pragma unroll
    for (int r = 0; r < 16; r++) { gi[r][k] = ai[r] + bi; gh[r][k] = ah[r] + bh; }
    __syncthreads();
    for (int i = tid; i < 16 * 64; i += 192) {
        int r = i >> 6, kk = i & 63;
        float ir = gi[r][kk],      hr = gh[r][kk];
        float iz = gi[r][64 + kk], hz = gh[r][64 + kk];
        float ig = gi[r][128 + kk], hg = gh[r][128 + kk];
        float rr = 1.f / (1.f + expf(-(ir + hr)));
        float zz = 1.f / (1.f + expf(-(iz + hz)));
        float gg = tanhf(ig + rr * hg);
        float hn = (1.f - zz) * gg + zz * sh[r][kk];
        int n = n0 + r;
        g_hgru[n * 64 + kk] = hn;
        if (outp) outp[n * 64 + kk] = hn;
    }
}

// ---------------- output writers ------------------------------------------------
__global__ void k_write_edges(const void* __restrict__ ei, float* __restrict__ out,
                              int mode) {
    int e = blockIdx.x * 256 + threadIdx.x;
    if (e >= EP) return;
    int s = (e < Ee) ? edge_val(ei, e) : (e - Ee);
    int d = (e < Ee) ? edge_val(ei, Ee + e) : (e - Ee);
    size_t base = (size_t)Nn * 64 + (size_t)EP * 4;
    if (mode == 1) {
        long long* p = (long long*)(out + base);
        p[e] = (long long)s;
        p[EP + e] = (long long)d;
    } else {
        out[base + e] = (float)s;
        out[base + EP + e] = (float)d;
    }
}

// ---------------- host launch ---------------------------------------------------
extern "C" void kernel_launch(void* const* d_in, const int* in_sizes, int n_in,
                              void* d_out, int out_size) {
    const float* x      = (const float*)d_in[0];
    const void*  ei     = (const void*)d_in[1];
    const float* W0     = (const float*)d_in[2];
    const float* a_src0 = (const float*)d_in[3];
    const float* a_dst0 = (const float*)d_in[4];
    const float* b0     = (const float*)d_in[5];
    const float* W1     = (const float*)d_in[6];
    const float* a_src1 = (const float*)d_in[7];
    const float* a_dst1 = (const float*)d_in[8];
    const float* b1     = (const float*)d_in[9];
    const float* ln_g   = (const float*)d_in[10];
    const float* ln_b   = (const float*)d_in[11];
    const float* W_ih   = (const float*)d_in[12];
    const float* W_hh   = (const float*)d_in[13];
    const float* b_ih   = (const float*)d_in[14];
    const float* b_hh   = (const float*)d_in[15];

    float* out = (float*)d_out;

    const int EB  = (EP + 255) / 256;
    const int NB16 = Nn / 16;                 // 625
    const int SMB = (Nn * 32 + 255) / 256;    // warp-per-node grid = 1250

    k_detect<<<1, 32>>>((const int*)ei);
    k_init<<<(Nn * 64 + 255) / 256, 256>>>(W_ih, W_hh);
    k_count<<<EB, 256>>>(ei);
    k_scan<<<1, 1024>>>();
    k_scatter<<<EB, 256>>>(ei);

    bool haveAlpha = (long long)out_size >= (long long)Nn * 64 + (long long)EP * 4;

    for (int t = 0; t < Tt; t++) {
        // layer 0
        k_l0_gemm<<<NB16, 256>>>(x, W0, a_src0, a_dst0, t);
        k_softmax_fused<<<SMB, 256>>>(nullptr);
        k_aggr0<<<Nn, 64>>>(b0);
        // layer 1
        k_l1_gemm<<<NB16, 256>>>(W1, a_src1, a_dst1);
        float* oa = (t == Tt - 1 && haveAlpha) ? (out + (size_t)Nn * 64) : nullptr;
        k_softmax_fused<<<SMB, 256>>>(oa);
        k_aggr1<<<Nn, 256>>>(b1, ln_g, ln_b);
        // GRU step
        float* outp = (t == Tt - 1) ? out : nullptr;
        k_gru<<<NB16, 192>>>(b_ih, b_hh, outp);
    }

    long long tail = (long long)out_size - ((long long)Nn * 64 + (long long)EP * 4);
    if (tail >= 4LL * EP) {
        k_write_edges<<<EB, 256>>>(ei, out, 1);
    } else if (tail >= 2LL * EP) {
        k_write_edges<<<EB, 256>>>(ei, out, 0);
    }
}